// round 1
// baseline (speedup 1.0000x reference)
#include <cuda_runtime.h>
#include <math.h>

// Problem constants (fixed by reference setup_inputs)
#define BB 4
#define HH 8
#define SS 2048
#define DD 8
#define CAP 64

// Scratch (no allocations allowed in kernel_launch)
__device__ float g_q[BB*HH*SS*DD];   // q projections, 2 MB
__device__ float g_k[BB*HH*SS*DD];   // k projections, 2 MB
__device__ int   g_cand[BB*SS*CAP];  // candidate key indices per (b,q) row
__device__ int   g_cnt[BB*SS];       // candidate counts per (b,q) row
__device__ unsigned g_qn2;           // max ||q||^2 over all rows (float bits)
__device__ unsigned g_kn2;           // max ||k||^2 over all rows (float bits)

__global__ void k_init() { g_qn2 = 0u; g_kn2 = 0u; }

// ---------------------------------------------------------------------------
// Kernel 1: q/k projections + global norm bounds.
// One thread per (b,h,s) row of 8 elements. 65536 threads.
// q[i] = sum_j x[j]*Wq[i,j] + bq[i]   (x @ Wq.T + bq)
// ---------------------------------------------------------------------------
__global__ void k_proj(const float* __restrict__ x,
                       const float* __restrict__ Wq, const float* __restrict__ bq,
                       const float* __restrict__ Wk, const float* __restrict__ bk) {
    __shared__ float sWq[64], sWk[64], sbq[8], sbk[8];
    int t = threadIdx.x;
    if (t < 64) { sWq[t] = Wq[t]; sWk[t] = Wk[t]; }
    if (t < 8)  { sbq[t] = bq[t]; sbk[t] = bk[t]; }
    __syncthreads();

    int row = blockIdx.x * blockDim.x + t;   // < BB*HH*SS
    const float4* xr = (const float4*)(x + (size_t)row * DD);
    float4 a = xr[0], b2 = xr[1];
    float xv[8] = {a.x, a.y, a.z, a.w, b2.x, b2.y, b2.z, b2.w};

    float qv[8], kv[8], qn = 0.f, kn = 0.f;
#pragma unroll
    for (int i = 0; i < 8; i++) {
        float aq = sbq[i], ak = sbk[i];
#pragma unroll
        for (int j = 0; j < 8; j++) {
            aq += xv[j] * sWq[i*8 + j];
            ak += xv[j] * sWk[i*8 + j];
        }
        qv[i] = aq; kv[i] = ak;
        qn += aq*aq; kn += ak*ak;
    }

    float4* qo = (float4*)(g_q + (size_t)row * DD);
    qo[0] = make_float4(qv[0], qv[1], qv[2], qv[3]);
    qo[1] = make_float4(qv[4], qv[5], qv[6], qv[7]);
    float4* ko = (float4*)(g_k + (size_t)row * DD);
    ko[0] = make_float4(kv[0], kv[1], kv[2], kv[3]);
    ko[1] = make_float4(kv[4], kv[5], kv[6], kv[7]);

    // warp-reduce max of norms, one atomic per warp (positive floats: uint order ok)
#pragma unroll
    for (int o = 16; o; o >>= 1) {
        qn = fmaxf(qn, __shfl_xor_sync(0xffffffffu, qn, o));
        kn = fmaxf(kn, __shfl_xor_sync(0xffffffffu, kn, o));
    }
    if ((t & 31) == 0) {
        atomicMax(&g_qn2, __float_as_uint(qn));
        atomicMax(&g_kn2, __float_as_uint(kn));
    }
}

// ---------------------------------------------------------------------------
// Kernel 2: per (b,q) row mask scan (shared across heads).
// Finds min(mask) over the 2048 keys, then gathers candidates
//   mask_k <= mask_min + (2*qk_bound + 30)/10000
// Every dropped key provably contributes < e^-30 relative softmax weight.
// One block (256 threads) per row; 8 floats/thread via 2x float4.
// ---------------------------------------------------------------------------
__global__ void k_cand(const float* __restrict__ mask) {
    int row = blockIdx.x;                      // b*SS + q
    int t = threadIdx.x;                       // 256
    const float4* mr = (const float4*)(mask + (size_t)row * SS);
    float4 m0 = mr[t*2], m1 = mr[t*2 + 1];
    float v[8] = {m0.x, m0.y, m0.z, m0.w, m1.x, m1.y, m1.z, m1.w};

    float mn = v[0];
#pragma unroll
    for (int j = 1; j < 8; j++) mn = fminf(mn, v[j]);

    __shared__ float warpmin[8];
    __shared__ float s_thresh;
    __shared__ int   s_cnt;
    __shared__ int   s_idx[CAP];
#pragma unroll
    for (int o = 16; o; o >>= 1) mn = fminf(mn, __shfl_xor_sync(0xffffffffu, mn, o));
    if ((t & 31) == 0) warpmin[t >> 5] = mn;
    __syncthreads();
    if (t == 0) {
        float m = warpmin[0];
#pragma unroll
        for (int i = 1; i < 8; i++) m = fminf(m, warpmin[i]);
        // rigorous bound on |q.k| * (1/sqrt(8))
        float qb = sqrtf(__uint_as_float(g_qn2) * __uint_as_float(g_kn2)) * 0.35355339059f;
        s_thresh = m + (2.0f * qb + 30.0f) * 1e-4f;
        s_cnt = 0;
    }
    __syncthreads();

    float th = s_thresh;
#pragma unroll
    for (int j = 0; j < 8; j++) {
        if (v[j] <= th) {
            int p = atomicAdd(&s_cnt, 1);
            if (p < CAP) s_idx[p] = t*8 + j;
        }
    }
    __syncthreads();
    if (t == 0) g_cnt[row] = s_cnt;
    if (t < CAP && t < s_cnt) g_cand[(size_t)row * CAP + t] = s_idx[t];
}

// ---------------------------------------------------------------------------
// Kernel 3: exact softmax over candidates, output = sum p_k * x[b,h,k,:].
// One thread per (b,h,q) row. Falls back to the full 2048-key loop if the
// candidate list overflowed (cnt > CAP) -- exact in that case too.
// ---------------------------------------------------------------------------
__global__ void k_attn(const float* __restrict__ x, const float* __restrict__ mask,
                       float* __restrict__ out) {
    int idx = blockIdx.x * blockDim.x + threadIdx.x;  // < BB*HH*SS
    int s  = idx & (SS - 1);
    int bh = idx >> 11;          // b*HH + h
    int b  = bh >> 3;
    int rowbq = b * SS + s;

    int cnt = g_cnt[rowbq];
    bool full = (cnt > CAP);
    int n = full ? SS : cnt;

    const float4* qr = (const float4*)(g_q + (size_t)idx * DD);
    float4 q0 = qr[0], q1 = qr[1];

    const float* kbase = g_k + (size_t)bh * SS * DD;
    const float* xbase = x   + (size_t)bh * SS * DD;
    const float* mrow  = mask + (size_t)rowbq * SS;
    const int*   cl    = g_cand + (size_t)rowbq * CAP;

    float m = -INFINITY, l = 0.f;
    float acc[8] = {0,0,0,0,0,0,0,0};

    for (int i = 0; i < n; i++) {
        int kk = full ? i : cl[i];
        const float4* kr = (const float4*)(kbase + (size_t)kk * DD);
        float4 k0 = kr[0], k1 = kr[1];
        float sdot = q0.x*k0.x + q0.y*k0.y + q0.z*k0.z + q0.w*k0.w
                   + q1.x*k1.x + q1.y*k1.y + q1.z*k1.z + q1.w*k1.w;
        float sc = sdot * 0.35355339059f - 10000.0f * mrow[kk];

        float nm = fmaxf(m, sc);
        float corr = expf(m - nm);     // first iter: exp(-inf)=0, safe
        float p = expf(sc - nm);
        l = l * corr + p;

        const float4* xr = (const float4*)(xbase + (size_t)kk * DD);
        float4 x0 = xr[0], x1 = xr[1];
        acc[0] = acc[0]*corr + p*x0.x;
        acc[1] = acc[1]*corr + p*x0.y;
        acc[2] = acc[2]*corr + p*x0.z;
        acc[3] = acc[3]*corr + p*x0.w;
        acc[4] = acc[4]*corr + p*x1.x;
        acc[5] = acc[5]*corr + p*x1.y;
        acc[6] = acc[6]*corr + p*x1.z;
        acc[7] = acc[7]*corr + p*x1.w;
        m = nm;
    }

    float inv = 1.0f / l;
    float4* o = (float4*)(out + (size_t)idx * DD);
    o[0] = make_float4(acc[0]*inv, acc[1]*inv, acc[2]*inv, acc[3]*inv);
    o[1] = make_float4(acc[4]*inv, acc[5]*inv, acc[6]*inv, acc[7]*inv);
}

extern "C" void kernel_launch(void* const* d_in, const int* in_sizes, int n_in,
                              void* d_out, int out_size) {
    const float* x    = (const float*)d_in[0];  // [4,8,2048,8]
    const float* mask = (const float*)d_in[1];  // [4,1,2048,2048]
    const float* Wq   = (const float*)d_in[2];  // [8,8]
    const float* bq   = (const float*)d_in[3];  // [8]
    const float* Wk   = (const float*)d_in[4];  // [8,8]
    const float* bk   = (const float*)d_in[5];  // [8]
    float* out = (float*)d_out;                 // [4,8,2048,8]

    k_init<<<1, 1>>>();
    k_proj<<<(BB*HH*SS)/256, 256>>>(x, Wq, bq, Wk, bk);
    k_cand<<<BB*SS, 256>>>(mask);
    k_attn<<<(BB*HH*SS)/256, 256>>>(x, mask, out);
}